// round 2
// baseline (speedup 1.0000x reference)
#include <cuda_runtime.h>
#include <cuda_bf16.h>
#include <math.h>

// ---------------------------------------------------------------------------
// Problem constants
// ---------------------------------------------------------------------------
#define L_LAYERS 6
#define V_VOCAB  512
#define D_MODEL  768
#define P_PROJ   768
#define N_HEADS  12
#define HD       64
#define FF_DIM   3072
#define B_BATCH  8
#define T_SEQ    1024
#define ROWS     (B_BATCH * T_SEQ)   // 8192
#define LN_EPS   1e-5f

// ---------------------------------------------------------------------------
// Scratch (device globals: allocation-free rule)
// ---------------------------------------------------------------------------
__device__ float g_x [ROWS * D_MODEL];
__device__ float g_h [ROWS * D_MODEL];
__device__ float g_q [ROWS * P_PROJ];
__device__ float g_k [ROWS * P_PROJ];
__device__ float g_v [ROWS * P_PROJ];
__device__ float g_y [ROWS * P_PROJ];
__device__ float g_m1[ROWS * FF_DIM];

// ---------------------------------------------------------------------------
// Embedding: x[r, :] = tok_emb[idx[r], :] + pos_emb[r % T, :]
// ---------------------------------------------------------------------------
__global__ void embed_kernel(const int* __restrict__ idx,
                             const float* __restrict__ tok,
                             const float* __restrict__ pos,
                             float* __restrict__ x)
{
    int r = blockIdx.x;                 // 0..8191
    int t = r & (T_SEQ - 1);
    int token = idx[r];
    const float* te = tok + (size_t)token * D_MODEL;
    const float* pe = pos + (size_t)t * D_MODEL;
    float* xr = x + (size_t)r * D_MODEL;
    for (int c = threadIdx.x; c < D_MODEL; c += 256)
        xr[c] = te[c] + pe[c];
}

// ---------------------------------------------------------------------------
// LayerNorm: one block (256 thr) per row of 768
// ---------------------------------------------------------------------------
__global__ __launch_bounds__(256) void layernorm_kernel(
    const float* __restrict__ x, const float* __restrict__ g,
    const float* __restrict__ b, float* __restrict__ o)
{
    int row = blockIdx.x;
    const float* xr = x + (size_t)row * D_MODEL;
    int t = threadIdx.x;
    float v0 = xr[t], v1 = xr[t + 256], v2 = xr[t + 512];
    float s  = v0 + v1 + v2;
    float sq = v0 * v0 + v1 * v1 + v2 * v2;
    #pragma unroll
    for (int off = 16; off > 0; off >>= 1) {
        s  += __shfl_xor_sync(0xffffffffu, s,  off);
        sq += __shfl_xor_sync(0xffffffffu, sq, off);
    }
    __shared__ float ss[8], sqq[8];
    if ((t & 31) == 0) { ss[t >> 5] = s; sqq[t >> 5] = sq; }
    __syncthreads();
    float ts = 0.f, tsq = 0.f;
    #pragma unroll
    for (int i = 0; i < 8; i++) { ts += ss[i]; tsq += sqq[i]; }
    const float inv = 1.0f / (float)D_MODEL;
    float mu  = ts * inv;
    float var = tsq * inv - mu * mu;
    float r   = rsqrtf(var + LN_EPS);
    float* orow = o + (size_t)row * D_MODEL;
    orow[t]       = (v0 - mu) * r * g[t]       + b[t];
    orow[t + 256] = (v1 - mu) * r * g[t + 256] + b[t + 256];
    orow[t + 512] = (v2 - mu) * r * g[t + 512] + b[t + 512];
}

// ---------------------------------------------------------------------------
// SGEMM: C[M,N] = A[M,K] @ B[K,N] (+bias) (+gelu) (+residual)
// 128x128 tile, BK=8, 256 threads, 8x8 per-thread, register prefetch.
// Requires M%128==0, N%128==0, K%8==0 (true for all shapes here).
// EPI: 0 = +bias, 1 = +bias then exact GELU, 2 = +bias +residual, 3 = plain
// ---------------------------------------------------------------------------
template <int EPI>
__global__ __launch_bounds__(256) void sgemm_kernel(
    const float* __restrict__ A, const float* __restrict__ B,
    const float* __restrict__ bias, const float* __restrict__ Res,
    float* __restrict__ C, int M, int N, int K)
{
    __shared__ float As[8][128];
    __shared__ float Bs[8][128];

    const int tid = threadIdx.x;
    const int bm = blockIdx.y * 128;
    const int bn = blockIdx.x * 128;
    const int tx = tid & 15;
    const int ty = tid >> 4;

    // load mapping
    const int ar = tid >> 1;           // 0..127 (A row within tile)
    const int ac = (tid & 1) * 4;      // 0 or 4 (A col within BK)
    const int br = tid >> 5;           // 0..7   (B row within BK)
    const int bc = (tid & 31) * 4;     // 0..124 (B col within tile)

    const float* Aptr = A + (size_t)(bm + ar) * K + ac;
    const float* Bptr = B + (size_t)br * N + bn + bc;

    float4 aReg = *(const float4*)Aptr;
    float4 bReg = *(const float4*)Bptr;

    float acc[8][8];
    #pragma unroll
    for (int i = 0; i < 8; i++)
        #pragma unroll
        for (int j = 0; j < 8; j++) acc[i][j] = 0.f;

    for (int kk = 0; kk < K; kk += 8) {
        As[ac + 0][ar] = aReg.x;
        As[ac + 1][ar] = aReg.y;
        As[ac + 2][ar] = aReg.z;
        As[ac + 3][ar] = aReg.w;
        *(float4*)&Bs[br][bc] = bReg;
        __syncthreads();

        if (kk + 8 < K) {
            aReg = *(const float4*)(Aptr + kk + 8);
            bReg = *(const float4*)(Bptr + (size_t)(kk + 8) * N);
        }

        #pragma unroll
        for (int k = 0; k < 8; k++) {
            float a[8], b[8];
            #pragma unroll
            for (int i = 0; i < 8; i++) a[i] = As[k][ty + i * 16];
            #pragma unroll
            for (int j = 0; j < 8; j++) b[j] = Bs[k][tx + j * 16];
            #pragma unroll
            for (int i = 0; i < 8; i++)
                #pragma unroll
                for (int j = 0; j < 8; j++)
                    acc[i][j] = fmaf(a[i], b[j], acc[i][j]);
        }
        __syncthreads();
    }

    #pragma unroll
    for (int i = 0; i < 8; i++) {
        int row = bm + ty + i * 16;
        #pragma unroll
        for (int j = 0; j < 8; j++) {
            int col = bn + tx + j * 16;
            float v = acc[i][j];
            if (EPI != 3) v += bias[col];
            if (EPI == 1) v = 0.5f * v * (1.0f + erff(v * 0.70710678118654752f));
            if (EPI == 2) v += Res[(size_t)row * N + col];
            C[(size_t)row * N + col] = v;
        }
    }
}

// ---------------------------------------------------------------------------
// Attention: streaming softmax, causal + attn_mask.
// Block: 128 threads handles one (b, h, 32-query tile). Key tiles of 32.
// Thread t: query ql = t>>2, segment seg = t&3. Each thread owns keys
// j*4+seg (j=0..7) and the full 64-dim accumulator for those keys;
// cross-seg reduce via shfl at the end.
// q/k/v/y layout: [B, T, H, HD] contiguous.
// ---------------------------------------------------------------------------
__global__ __launch_bounds__(128) void attn_kernel(
    const float* __restrict__ Q, const float* __restrict__ K,
    const float* __restrict__ V, const float* __restrict__ mask,
    float* __restrict__ Y)
{
    const int b  = blockIdx.y / N_HEADS;
    const int h  = blockIdx.y % N_HEADS;
    const int qb = blockIdx.x * 32;

    __shared__ float Qs[32][68];
    __shared__ float Ks[32][68];
    __shared__ float Vs[32][68];
    __shared__ float Ms[32];

    const int tid = threadIdx.x;
    const int ql  = tid >> 2;
    const int seg = tid & 3;

    // Load Q tile (scale folded in)
    #pragma unroll
    for (int i = 0; i < 4; i++) {
        int f = tid + i * 128;            // float4 id 0..511
        int r = f >> 4, c4 = (f & 15) << 2;
        size_t gi = (((size_t)b * T_SEQ + qb + r) * N_HEADS + h) * HD + c4;
        float4 qv = *(const float4*)&Q[gi];
        qv.x *= 0.125f; qv.y *= 0.125f; qv.z *= 0.125f; qv.w *= 0.125f;
        *(float4*)&Qs[r][c4] = qv;
    }

    float m = -1e30f, l = 0.f;
    float acc[64];
    #pragma unroll
    for (int d = 0; d < 64; d++) acc[d] = 0.f;

    for (int kb = 0; kb <= qb + 31; kb += 32) {
        __syncthreads();
        #pragma unroll
        for (int i = 0; i < 4; i++) {
            int f = tid + i * 128;
            int r = f >> 4, c4 = (f & 15) << 2;
            size_t gi = (((size_t)b * T_SEQ + kb + r) * N_HEADS + h) * HD + c4;
            *(float4*)&Ks[r][c4] = *(const float4*)&K[gi];
            *(float4*)&Vs[r][c4] = *(const float4*)&V[gi];
        }
        if (tid < 32) Ms[tid] = mask[b * T_SEQ + kb + tid];
        __syncthreads();

        // scores for this thread's 8 keys
        float s[8];
        #pragma unroll
        for (int j = 0; j < 8; j++) s[j] = 0.f;
        #pragma unroll
        for (int d4 = 0; d4 < 16; d4++) {
            float4 qv = *(const float4*)&Qs[ql][d4 * 4];
            #pragma unroll
            for (int j = 0; j < 8; j++) {
                float4 kv = *(const float4*)&Ks[j * 4 + seg][d4 * 4];
                s[j] = fmaf(qv.x, kv.x, fmaf(qv.y, kv.y,
                       fmaf(qv.z, kv.z, fmaf(qv.w, kv.w, s[j]))));
            }
        }
        #pragma unroll
        for (int j = 0; j < 8; j++) {
            int kl = j * 4 + seg;
            int kg = kb + kl;
            if (kg > qb + ql || Ms[kl] == 0.f) s[j] = -1e30f;
        }

        float tm = s[0];
        #pragma unroll
        for (int j = 1; j < 8; j++) tm = fmaxf(tm, s[j]);
        tm = fmaxf(tm, __shfl_xor_sync(0xffffffffu, tm, 1));
        tm = fmaxf(tm, __shfl_xor_sync(0xffffffffu, tm, 2));

        float nm   = fmaxf(m, tm);
        float corr = __expf(m - nm);
        float p[8], ps = 0.f;
        #pragma unroll
        for (int j = 0; j < 8; j++) { p[j] = __expf(s[j] - nm); ps += p[j]; }
        ps += __shfl_xor_sync(0xffffffffu, ps, 1);
        ps += __shfl_xor_sync(0xffffffffu, ps, 2);
        l = l * corr + ps;
        m = nm;

        #pragma unroll
        for (int d4 = 0; d4 < 16; d4++) {
            float ax = acc[d4 * 4 + 0] * corr;
            float ay = acc[d4 * 4 + 1] * corr;
            float az = acc[d4 * 4 + 2] * corr;
            float aw = acc[d4 * 4 + 3] * corr;
            #pragma unroll
            for (int j = 0; j < 8; j++) {
                float4 vv = *(const float4*)&Vs[j * 4 + seg][d4 * 4];
                ax = fmaf(p[j], vv.x, ax);
                ay = fmaf(p[j], vv.y, ay);
                az = fmaf(p[j], vv.z, az);
                aw = fmaf(p[j], vv.w, aw);
            }
            acc[d4 * 4 + 0] = ax; acc[d4 * 4 + 1] = ay;
            acc[d4 * 4 + 2] = az; acc[d4 * 4 + 3] = aw;
        }
    }

    float invl = 1.0f / l;
    size_t ybase = (((size_t)b * T_SEQ + qb + ql) * N_HEADS + h) * HD;
    #pragma unroll
    for (int d = 0; d < 64; d++) {
        float v = acc[d];
        v += __shfl_xor_sync(0xffffffffu, v, 1);
        v += __shfl_xor_sync(0xffffffffu, v, 2);
        if (seg == (d & 3)) Y[ybase + d] = v * invl;
    }
}

// ---------------------------------------------------------------------------
// Host orchestration
// ---------------------------------------------------------------------------
extern "C" void kernel_launch(void* const* d_in, const int* in_sizes, int n_in,
                              void* d_out, int out_size)
{
    const int*   idx       = (const int*)  d_in[0];
    const float* attn_mask = (const float*)d_in[1];
    const float* tok_emb   = (const float*)d_in[2];
    const float* pos_emb   = (const float*)d_in[3];
    const float* ln1_g     = (const float*)d_in[4];
    const float* ln1_b     = (const float*)d_in[5];
    const float* Wq        = (const float*)d_in[6];
    const float* bq        = (const float*)d_in[7];
    const float* Wk        = (const float*)d_in[8];
    const float* bk        = (const float*)d_in[9];
    const float* Wv        = (const float*)d_in[10];
    const float* bv        = (const float*)d_in[11];
    const float* Wo        = (const float*)d_in[12];
    const float* bo        = (const float*)d_in[13];
    const float* ln2_g     = (const float*)d_in[14];
    const float* ln2_b     = (const float*)d_in[15];
    const float* W1        = (const float*)d_in[16];
    const float* b1        = (const float*)d_in[17];
    const float* W2        = (const float*)d_in[18];
    const float* b2        = (const float*)d_in[19];
    const float* lnf_g     = (const float*)d_in[20];
    const float* lnf_b     = (const float*)d_in[21];
    const float* W_out     = (const float*)d_in[22];
    float* out = (float*)d_out;

    float *x, *h, *q, *k, *v, *y, *m1;
    cudaGetSymbolAddress((void**)&x,  g_x);
    cudaGetSymbolAddress((void**)&h,  g_h);
    cudaGetSymbolAddress((void**)&q,  g_q);
    cudaGetSymbolAddress((void**)&k,  g_k);
    cudaGetSymbolAddress((void**)&v,  g_v);
    cudaGetSymbolAddress((void**)&y,  g_y);
    cudaGetSymbolAddress((void**)&m1, g_m1);

    const dim3 g768 (P_PROJ / 128, ROWS / 128);   // (6, 64)
    const dim3 gff  (FF_DIM / 128, ROWS / 128);   // (24, 64)
    const dim3 ghead(V_VOCAB / 128, ROWS / 128);  // (4, 64)
    const dim3 gattn(T_SEQ / 32, B_BATCH * N_HEADS);

    embed_kernel<<<ROWS, 256>>>(idx, tok_emb, pos_emb, x);

    for (int l = 0; l < L_LAYERS; l++) {
        const size_t wqkv = (size_t)l * D_MODEL * P_PROJ;

        layernorm_kernel<<<ROWS, 256>>>(x, ln1_g + l * D_MODEL, ln1_b + l * D_MODEL, h);

        sgemm_kernel<0><<<g768, 256>>>(h, Wq + wqkv, bq + l * P_PROJ, nullptr, q,
                                       ROWS, P_PROJ, D_MODEL);
        sgemm_kernel<0><<<g768, 256>>>(h, Wk + wqkv, bk + l * P_PROJ, nullptr, k,
                                       ROWS, P_PROJ, D_MODEL);
        sgemm_kernel<0><<<g768, 256>>>(h, Wv + wqkv, bv + l * P_PROJ, nullptr, v,
                                       ROWS, P_PROJ, D_MODEL);

        attn_kernel<<<gattn, 128>>>(q, k, v, attn_mask, y);

        // x = x + y @ Wo + bo
        sgemm_kernel<2><<<g768, 256>>>(y, Wo + (size_t)l * P_PROJ * D_MODEL,
                                       bo + l * D_MODEL, x, x,
                                       ROWS, D_MODEL, P_PROJ);

        layernorm_kernel<<<ROWS, 256>>>(x, ln2_g + l * D_MODEL, ln2_b + l * D_MODEL, h);

        // m1 = gelu(h @ W1 + b1)
        sgemm_kernel<1><<<gff, 256>>>(h, W1 + (size_t)l * D_MODEL * FF_DIM,
                                      b1 + l * FF_DIM, nullptr, m1,
                                      ROWS, FF_DIM, D_MODEL);
        // x = x + m1 @ W2 + b2
        sgemm_kernel<2><<<g768, 256>>>(m1, W2 + (size_t)l * FF_DIM * D_MODEL,
                                       b2 + l * D_MODEL, x, x,
                                       ROWS, D_MODEL, FF_DIM);
    }

    layernorm_kernel<<<ROWS, 256>>>(x, lnf_g, lnf_b, h);
    sgemm_kernel<3><<<ghead, 256>>>(h, W_out, nullptr, nullptr, out,
                                    ROWS, V_VOCAB, D_MODEL);
}

// round 3
// speedup vs baseline: 2.1576x; 2.1576x over previous
#include <cuda_runtime.h>
#include <cuda_bf16.h>
#include <math.h>
#include <stdint.h>

// ---------------------------------------------------------------------------
// Problem constants
// ---------------------------------------------------------------------------
#define L_LAYERS 6
#define V_VOCAB  512
#define D_MODEL  768
#define P_PROJ   768
#define N_HEADS  12
#define HD       64
#define FF_DIM   3072
#define B_BATCH  8
#define T_SEQ    1024
#define ROWS     (B_BATCH * T_SEQ)   // 8192
#define LN_EPS   1e-5f

// ---------------------------------------------------------------------------
// Scratch (device globals: allocation-free rule)
// ---------------------------------------------------------------------------
__device__ float g_x [ROWS * D_MODEL];           // residual stream (fp32)
__device__ float g_q [ROWS * P_PROJ];
__device__ float g_k [ROWS * P_PROJ];
__device__ float g_v [ROWS * P_PROJ];

__device__ __nv_bfloat16 g_h_hi [ROWS * D_MODEL];
__device__ __nv_bfloat16 g_h_lo [ROWS * D_MODEL];
__device__ __nv_bfloat16 g_y_hi [ROWS * P_PROJ];
__device__ __nv_bfloat16 g_y_lo [ROWS * P_PROJ];
__device__ __nv_bfloat16 g_m1_hi[ROWS * FF_DIM];
__device__ __nv_bfloat16 g_m1_lo[ROWS * FF_DIM];

// split weights
__device__ __nv_bfloat16 g_wq_hi[L_LAYERS * D_MODEL * P_PROJ];
__device__ __nv_bfloat16 g_wq_lo[L_LAYERS * D_MODEL * P_PROJ];
__device__ __nv_bfloat16 g_wk_hi[L_LAYERS * D_MODEL * P_PROJ];
__device__ __nv_bfloat16 g_wk_lo[L_LAYERS * D_MODEL * P_PROJ];
__device__ __nv_bfloat16 g_wv_hi[L_LAYERS * D_MODEL * P_PROJ];
__device__ __nv_bfloat16 g_wv_lo[L_LAYERS * D_MODEL * P_PROJ];
__device__ __nv_bfloat16 g_wo_hi[L_LAYERS * P_PROJ * D_MODEL];
__device__ __nv_bfloat16 g_wo_lo[L_LAYERS * P_PROJ * D_MODEL];
__device__ __nv_bfloat16 g_w1_hi[L_LAYERS * D_MODEL * FF_DIM];
__device__ __nv_bfloat16 g_w1_lo[L_LAYERS * D_MODEL * FF_DIM];
__device__ __nv_bfloat16 g_w2_hi[L_LAYERS * FF_DIM * D_MODEL];
__device__ __nv_bfloat16 g_w2_lo[L_LAYERS * FF_DIM * D_MODEL];
__device__ __nv_bfloat16 g_wout_hi[D_MODEL * V_VOCAB];
__device__ __nv_bfloat16 g_wout_lo[D_MODEL * V_VOCAB];

// ---------------------------------------------------------------------------
// Small helpers
// ---------------------------------------------------------------------------
__device__ __forceinline__ uint32_t smem_u32(const void* p) {
    return (uint32_t)__cvta_generic_to_shared(p);
}
__device__ __forceinline__ void cp_async16(uint32_t dst, const void* src) {
    asm volatile("cp.async.cg.shared.global [%0], [%1], 16;" :: "r"(dst), "l"(src));
}
__device__ __forceinline__ void cp_commit() {
    asm volatile("cp.async.commit_group;");
}
__device__ __forceinline__ void cp_wait1() {
    asm volatile("cp.async.wait_group 1;" ::: "memory");
}
__device__ __forceinline__ void cp_wait0() {
    asm volatile("cp.async.wait_group 0;" ::: "memory");
}
__device__ __forceinline__ void ldsm_x4(uint32_t* r, uint32_t addr) {
    asm volatile("ldmatrix.sync.aligned.m8n8.x4.shared.b16 {%0,%1,%2,%3}, [%4];"
                 : "=r"(r[0]), "=r"(r[1]), "=r"(r[2]), "=r"(r[3]) : "r"(addr));
}
__device__ __forceinline__ void ldsm_x4_t(uint32_t* r, uint32_t addr) {
    asm volatile("ldmatrix.sync.aligned.m8n8.x4.trans.shared.b16 {%0,%1,%2,%3}, [%4];"
                 : "=r"(r[0]), "=r"(r[1]), "=r"(r[2]), "=r"(r[3]) : "r"(addr));
}
__device__ __forceinline__ void mma_bf16(float* d, const uint32_t* a, uint32_t b0, uint32_t b1) {
    asm volatile("mma.sync.aligned.m16n8k16.row.col.f32.bf16.bf16.f32 "
                 "{%0,%1,%2,%3}, {%4,%5,%6,%7}, {%8,%9}, {%0,%1,%2,%3};"
                 : "+f"(d[0]), "+f"(d[1]), "+f"(d[2]), "+f"(d[3])
                 : "r"(a[0]), "r"(a[1]), "r"(a[2]), "r"(a[3]), "r"(b0), "r"(b1));
}
__device__ __forceinline__ float gelu_exact(float v) {
    return 0.5f * v * (1.0f + erff(v * 0.70710678118654752f));
}
__device__ __forceinline__ void split_store2(__nv_bfloat16* Hi, __nv_bfloat16* Lo,
                                             size_t off, float a, float b) {
    __nv_bfloat16 ha = __float2bfloat16(a), hb = __float2bfloat16(b);
    __nv_bfloat162 hv; hv.x = ha; hv.y = hb;
    *(__nv_bfloat162*)(Hi + off) = hv;
    __nv_bfloat162 lv;
    lv.x = __float2bfloat16(a - __bfloat162float(ha));
    lv.y = __float2bfloat16(b - __bfloat162float(hb));
    *(__nv_bfloat162*)(Lo + off) = lv;
}

// ---------------------------------------------------------------------------
// Weight split: fp32 -> (hi, lo) bf16, vectorized x4
// ---------------------------------------------------------------------------
__global__ void split_kernel(const float4* __restrict__ src,
                             __nv_bfloat16* __restrict__ hi,
                             __nv_bfloat16* __restrict__ lo, int n4)
{
    int i = blockIdx.x * 256 + threadIdx.x;
    if (i >= n4) return;
    float4 v = src[i];
    size_t off = (size_t)i * 4;
    split_store2(hi, lo, off,     v.x, v.y);
    split_store2(hi, lo, off + 2, v.z, v.w);
}

// ---------------------------------------------------------------------------
// Embedding
// ---------------------------------------------------------------------------
__global__ void embed_kernel(const int* __restrict__ idx,
                             const float* __restrict__ tok,
                             const float* __restrict__ pos,
                             float* __restrict__ x)
{
    int r = blockIdx.x;
    int t = r & (T_SEQ - 1);
    int token = idx[r];
    const float* te = tok + (size_t)token * D_MODEL;
    const float* pe = pos + (size_t)t * D_MODEL;
    float* xr = x + (size_t)r * D_MODEL;
    for (int c = threadIdx.x; c < D_MODEL; c += 256)
        xr[c] = te[c] + pe[c];
}

// ---------------------------------------------------------------------------
// LayerNorm -> split bf16 (hi, lo) output
// ---------------------------------------------------------------------------
__global__ __launch_bounds__(256) void layernorm_split_kernel(
    const float* __restrict__ x, const float* __restrict__ g,
    const float* __restrict__ b,
    __nv_bfloat16* __restrict__ ohi, __nv_bfloat16* __restrict__ olo)
{
    int row = blockIdx.x;
    const float* xr = x + (size_t)row * D_MODEL;
    int t = threadIdx.x;
    float v0 = xr[t], v1 = xr[t + 256], v2 = xr[t + 512];
    float s  = v0 + v1 + v2;
    float sq = v0 * v0 + v1 * v1 + v2 * v2;
    #pragma unroll
    for (int off = 16; off > 0; off >>= 1) {
        s  += __shfl_xor_sync(0xffffffffu, s,  off);
        sq += __shfl_xor_sync(0xffffffffu, sq, off);
    }
    __shared__ float ss[8], sqq[8];
    if ((t & 31) == 0) { ss[t >> 5] = s; sqq[t >> 5] = sq; }
    __syncthreads();
    float ts = 0.f, tsq = 0.f;
    #pragma unroll
    for (int i = 0; i < 8; i++) { ts += ss[i]; tsq += sqq[i]; }
    const float inv = 1.0f / (float)D_MODEL;
    float mu  = ts * inv;
    float var = tsq * inv - mu * mu;
    float r   = rsqrtf(var + LN_EPS);

    size_t base = (size_t)row * D_MODEL;
    #pragma unroll
    for (int i = 0; i < 3; i++) {
        int c = t + i * 256;
        float v = (i == 0 ? v0 : (i == 1 ? v1 : v2));
        float o = (v - mu) * r * g[c] + b[c];
        __nv_bfloat16 h = __float2bfloat16(o);
        ohi[base + c] = h;
        olo[base + c] = __float2bfloat16(o - __bfloat162float(h));
    }
}

// ---------------------------------------------------------------------------
// Split-bf16 tensor-core GEMM: C[M,N] = (Ahi+Alo) @ (Bhi+Blo)  (fp32 accum)
// 128x128x32 CTA tile, 8 warps (4x2), warp tile 32x64, m16n8k16 bf16 mma,
// cp.async double buffering, padded smem pitches for conflict-free ldmatrix.
// EPI: 0 = +bias -> f32 C
//      1 = +bias, exact GELU -> split bf16 (Chi, Clo)
//      2 = +bias +Res -> f32 C
//      3 = plain -> f32 C
// ---------------------------------------------------------------------------
#define BM 128
#define BN 128
#define BK 32
#define PA 40    // A smem pitch in bf16 (80 bytes)
#define PB 136   // B smem pitch in bf16 (272 bytes)
#define AS_ELEMS (BM * PA)                         // 5120
#define BS_ELEMS (BK * PB)                         // 4352
#define STAGE_ELEMS (2 * AS_ELEMS + 2 * BS_ELEMS)  // 18944
#define GEMM_SMEM_BYTES (2 * STAGE_ELEMS * 2)      // 75776

template <int EPI>
__global__ __launch_bounds__(256) void hgemm_kernel(
    const __nv_bfloat16* __restrict__ Ahi, const __nv_bfloat16* __restrict__ Alo,
    const __nv_bfloat16* __restrict__ Bhi, const __nv_bfloat16* __restrict__ Blo,
    const float* __restrict__ bias, const float* __restrict__ Res,
    float* __restrict__ C,
    __nv_bfloat16* __restrict__ Chi, __nv_bfloat16* __restrict__ Clo,
    int M, int N, int K)
{
    extern __shared__ __nv_bfloat16 sm[];
    const uint32_t smem_base = smem_u32(sm);
    const uint32_t stage_bytes = STAGE_ELEMS * 2;
    const uint32_t offAhi = 0;
    const uint32_t offAlo = AS_ELEMS * 2;
    const uint32_t offBhi = 2 * AS_ELEMS * 2;
    const uint32_t offBlo = (2 * AS_ELEMS + BS_ELEMS) * 2;

    const int tid  = threadIdx.x;
    const int lane = tid & 31;
    const int wid  = tid >> 5;
    const int warp_m = wid >> 1;        // 0..3
    const int warp_n = wid & 1;         // 0..1
    const int bm = blockIdx.y * BM;
    const int bn = blockIdx.x * BN;

    // global->smem load mapping
    const int a_row = tid >> 2;         // 0..63 (+64 on second pass)
    const int a_q   = tid & 3;
    const int b_row = tid >> 4;         // 0..15 (+16 on second pass)
    const int b_q   = tid & 15;

    float acc[2][8][4];
    #pragma unroll
    for (int i = 0; i < 2; i++)
        #pragma unroll
        for (int j = 0; j < 8; j++)
            #pragma unroll
            for (int t = 0; t < 4; t++) acc[i][j][t] = 0.f;

    const int n_tiles = K / BK;

    // stage loader
    auto load_stage = [&](int s, int k0) {
        uint32_t base = smem_base + s * stage_bytes;
        #pragma unroll
        for (int j = 0; j < 2; j++) {
            int ar = a_row + j * 64;
            const __nv_bfloat16* srcA = Ahi + (size_t)(bm + ar) * K + k0 + a_q * 8;
            uint32_t dstA = base + offAhi + (ar * PA + a_q * 8) * 2;
            cp_async16(dstA, srcA);
            const __nv_bfloat16* srcAl = Alo + (size_t)(bm + ar) * K + k0 + a_q * 8;
            cp_async16(dstA + (offAlo - offAhi), srcAl);

            int br = b_row + j * 16;
            const __nv_bfloat16* srcB = Bhi + (size_t)(k0 + br) * N + bn + b_q * 8;
            uint32_t dstB = base + offBhi + (br * PB + b_q * 8) * 2;
            cp_async16(dstB, srcB);
            const __nv_bfloat16* srcBl = Blo + (size_t)(k0 + br) * N + bn + b_q * 8;
            cp_async16(dstB + (offBlo - offBhi), srcBl);
        }
    };

    load_stage(0, 0);
    cp_commit();

    const int lr = lane & 15;
    const int lc = (lane >> 4) * 8;

    for (int t = 0; t < n_tiles; t++) {
        int cur = t & 1;
        if (t + 1 < n_tiles) {
            load_stage((t + 1) & 1, (t + 1) * BK);
            cp_commit();
            cp_wait1();
        } else {
            cp_wait0();
        }
        __syncthreads();

        uint32_t base = smem_base + cur * stage_bytes;
        #pragma unroll
        for (int ks = 0; ks < BK; ks += 16) {
            uint32_t a_hi[2][4], a_lo[2][4];
            #pragma unroll
            for (int mi = 0; mi < 2; mi++) {
                uint32_t addr = base + offAhi +
                    ((warp_m * 32 + mi * 16 + lr) * PA + ks + lc) * 2;
                ldsm_x4(a_hi[mi], addr);
                ldsm_x4(a_lo[mi], addr + (offAlo - offAhi));
            }
            uint32_t b_hi[4][4], b_lo[4][4];
            #pragma unroll
            for (int bi = 0; bi < 4; bi++) {
                uint32_t addr = base + offBhi +
                    ((ks + lr) * PB + warp_n * 64 + bi * 16 + lc) * 2;
                ldsm_x4_t(b_hi[bi], addr);
                ldsm_x4_t(b_lo[bi], addr + (offBlo - offBhi));
            }
            #pragma unroll
            for (int mi = 0; mi < 2; mi++) {
                #pragma unroll
                for (int ni = 0; ni < 8; ni++) {
                    int bi = ni >> 1;
                    int hh = (ni & 1) * 2;
                    mma_bf16(acc[mi][ni], a_hi[mi], b_hi[bi][hh], b_hi[bi][hh + 1]);
                    mma_bf16(acc[mi][ni], a_hi[mi], b_lo[bi][hh], b_lo[bi][hh + 1]);
                    mma_bf16(acc[mi][ni], a_lo[mi], b_hi[bi][hh], b_hi[bi][hh + 1]);
                }
            }
        }
        __syncthreads();
    }

    // epilogue
    const int g = lane >> 2, tig = lane & 3;
    #pragma unroll
    for (int mi = 0; mi < 2; mi++) {
        #pragma unroll
        for (int ni = 0; ni < 8; ni++) {
            int r0 = bm + warp_m * 32 + mi * 16 + g;
            int r1 = r0 + 8;
            int c  = bn + warp_n * 64 + ni * 8 + tig * 2;
            float v00 = acc[mi][ni][0], v01 = acc[mi][ni][1];
            float v10 = acc[mi][ni][2], v11 = acc[mi][ni][3];
            if (EPI != 3) {
                float b0 = bias[c], b1 = bias[c + 1];
                v00 += b0; v01 += b1; v10 += b0; v11 += b1;
            }
            if (EPI == 1) {
                v00 = gelu_exact(v00); v01 = gelu_exact(v01);
                v10 = gelu_exact(v10); v11 = gelu_exact(v11);
                split_store2(Chi, Clo, (size_t)r0 * N + c, v00, v01);
                split_store2(Chi, Clo, (size_t)r1 * N + c, v10, v11);
            } else {
                if (EPI == 2) {
                    float2 z0 = *(const float2*)&Res[(size_t)r0 * N + c];
                    float2 z1 = *(const float2*)&Res[(size_t)r1 * N + c];
                    v00 += z0.x; v01 += z0.y; v10 += z1.x; v11 += z1.y;
                }
                float2 o0 = make_float2(v00, v01);
                float2 o1 = make_float2(v10, v11);
                *(float2*)&C[(size_t)r0 * N + c] = o0;
                *(float2*)&C[(size_t)r1 * N + c] = o1;
            }
        }
    }
}

// ---------------------------------------------------------------------------
// Attention (fp32 math, split bf16 output)
// ---------------------------------------------------------------------------
__global__ __launch_bounds__(128) void attn_kernel(
    const float* __restrict__ Q, const float* __restrict__ K,
    const float* __restrict__ V, const float* __restrict__ mask,
    __nv_bfloat16* __restrict__ Yhi, __nv_bfloat16* __restrict__ Ylo)
{
    const int b  = blockIdx.y / N_HEADS;
    const int h  = blockIdx.y % N_HEADS;
    const int qb = blockIdx.x * 32;

    __shared__ float Qs[32][68];
    __shared__ float Ks[32][68];
    __shared__ float Vs[32][68];
    __shared__ float Ms[32];

    const int tid = threadIdx.x;
    const int ql  = tid >> 2;
    const int seg = tid & 3;

    #pragma unroll
    for (int i = 0; i < 4; i++) {
        int f = tid + i * 128;
        int r = f >> 4, c4 = (f & 15) << 2;
        size_t gi = (((size_t)b * T_SEQ + qb + r) * N_HEADS + h) * HD + c4;
        float4 qv = *(const float4*)&Q[gi];
        qv.x *= 0.125f; qv.y *= 0.125f; qv.z *= 0.125f; qv.w *= 0.125f;
        *(float4*)&Qs[r][c4] = qv;
    }

    float m = -1e30f, l = 0.f;
    float acc[64];
    #pragma unroll
    for (int d = 0; d < 64; d++) acc[d] = 0.f;

    for (int kb = 0; kb <= qb + 31; kb += 32) {
        __syncthreads();
        #pragma unroll
        for (int i = 0; i < 4; i++) {
            int f = tid + i * 128;
            int r = f >> 4, c4 = (f & 15) << 2;
            size_t gi = (((size_t)b * T_SEQ + kb + r) * N_HEADS + h) * HD + c4;
            *(float4*)&Ks[r][c4] = *(const float4*)&K[gi];
            *(float4*)&Vs[r][c4] = *(const float4*)&V[gi];
        }
        if (tid < 32) Ms[tid] = mask[b * T_SEQ + kb + tid];
        __syncthreads();

        float s[8];
        #pragma unroll
        for (int j = 0; j < 8; j++) s[j] = 0.f;
        #pragma unroll
        for (int d4 = 0; d4 < 16; d4++) {
            float4 qv = *(const float4*)&Qs[ql][d4 * 4];
            #pragma unroll
            for (int j = 0; j < 8; j++) {
                float4 kv = *(const float4*)&Ks[j * 4 + seg][d4 * 4];
                s[j] = fmaf(qv.x, kv.x, fmaf(qv.y, kv.y,
                       fmaf(qv.z, kv.z, fmaf(qv.w, kv.w, s[j]))));
            }
        }
        #pragma unroll
        for (int j = 0; j < 8; j++) {
            int kl = j * 4 + seg;
            int kg = kb + kl;
            if (kg > qb + ql || Ms[kl] == 0.f) s[j] = -1e30f;
        }

        float tm = s[0];
        #pragma unroll
        for (int j = 1; j < 8; j++) tm = fmaxf(tm, s[j]);
        tm = fmaxf(tm, __shfl_xor_sync(0xffffffffu, tm, 1));
        tm = fmaxf(tm, __shfl_xor_sync(0xffffffffu, tm, 2));

        float nm   = fmaxf(m, tm);
        float corr = __expf(m - nm);
        float p[8], ps = 0.f;
        #pragma unroll
        for (int j = 0; j < 8; j++) { p[j] = __expf(s[j] - nm); ps += p[j]; }
        ps += __shfl_xor_sync(0xffffffffu, ps, 1);
        ps += __shfl_xor_sync(0xffffffffu, ps, 2);
        l = l * corr + ps;
        m = nm;

        #pragma unroll
        for (int d4 = 0; d4 < 16; d4++) {
            float ax = acc[d4 * 4 + 0] * corr;
            float ay = acc[d4 * 4 + 1] * corr;
            float az = acc[d4 * 4 + 2] * corr;
            float aw = acc[d4 * 4 + 3] * corr;
            #pragma unroll
            for (int j = 0; j < 8; j++) {
                float4 vv = *(const float4*)&Vs[j * 4 + seg][d4 * 4];
                ax = fmaf(p[j], vv.x, ax);
                ay = fmaf(p[j], vv.y, ay);
                az = fmaf(p[j], vv.z, az);
                aw = fmaf(p[j], vv.w, aw);
            }
            acc[d4 * 4 + 0] = ax; acc[d4 * 4 + 1] = ay;
            acc[d4 * 4 + 2] = az; acc[d4 * 4 + 3] = aw;
        }
    }

    float invl = 1.0f / l;
    size_t ybase = (((size_t)b * T_SEQ + qb + ql) * N_HEADS + h) * HD;
    #pragma unroll
    for (int d = 0; d < 64; d++) {
        float v = acc[d];
        v += __shfl_xor_sync(0xffffffffu, v, 1);
        v += __shfl_xor_sync(0xffffffffu, v, 2);
        if (seg == (d & 3)) {
            float o = v * invl;
            __nv_bfloat16 hh = __float2bfloat16(o);
            Yhi[ybase + d] = hh;
            Ylo[ybase + d] = __float2bfloat16(o - __bfloat162float(hh));
        }
    }
}

// ---------------------------------------------------------------------------
// Host orchestration
// ---------------------------------------------------------------------------
static void split_launch(const float* src, __nv_bfloat16* hi, __nv_bfloat16* lo, int n) {
    int n4 = n / 4;
    split_kernel<<<(n4 + 255) / 256, 256>>>((const float4*)src, hi, lo, n4);
}

extern "C" void kernel_launch(void* const* d_in, const int* in_sizes, int n_in,
                              void* d_out, int out_size)
{
    const int*   idx       = (const int*)  d_in[0];
    const float* attn_mask = (const float*)d_in[1];
    const float* tok_emb   = (const float*)d_in[2];
    const float* pos_emb   = (const float*)d_in[3];
    const float* ln1_g     = (const float*)d_in[4];
    const float* ln1_b     = (const float*)d_in[5];
    const float* Wq        = (const float*)d_in[6];
    const float* bq        = (const float*)d_in[7];
    const float* Wk        = (const float*)d_in[8];
    const float* bk        = (const float*)d_in[9];
    const float* Wv        = (const float*)d_in[10];
    const float* bv        = (const float*)d_in[11];
    const float* Wo        = (const float*)d_in[12];
    const float* bo        = (const float*)d_in[13];
    const float* ln2_g     = (const float*)d_in[14];
    const float* ln2_b     = (const float*)d_in[15];
    const float* W1        = (const float*)d_in[16];
    const float* b1        = (const float*)d_in[17];
    const float* W2        = (const float*)d_in[18];
    const float* b2        = (const float*)d_in[19];
    const float* lnf_g     = (const float*)d_in[20];
    const float* lnf_b     = (const float*)d_in[21];
    const float* W_out     = (const float*)d_in[22];
    float* out = (float*)d_out;

    float *x, *q, *k, *v;
    __nv_bfloat16 *h_hi, *h_lo, *y_hi, *y_lo, *m1_hi, *m1_lo;
    __nv_bfloat16 *wq_hi, *wq_lo, *wk_hi, *wk_lo, *wv_hi, *wv_lo;
    __nv_bfloat16 *wo_hi, *wo_lo, *w1_hi, *w1_lo, *w2_hi, *w2_lo, *wout_hi, *wout_lo;

    cudaGetSymbolAddress((void**)&x,  g_x);
    cudaGetSymbolAddress((void**)&q,  g_q);
    cudaGetSymbolAddress((void**)&k,  g_k);
    cudaGetSymbolAddress((void**)&v,  g_v);
    cudaGetSymbolAddress((void**)&h_hi,  g_h_hi);
    cudaGetSymbolAddress((void**)&h_lo,  g_h_lo);
    cudaGetSymbolAddress((void**)&y_hi,  g_y_hi);
    cudaGetSymbolAddress((void**)&y_lo,  g_y_lo);
    cudaGetSymbolAddress((void**)&m1_hi, g_m1_hi);
    cudaGetSymbolAddress((void**)&m1_lo, g_m1_lo);
    cudaGetSymbolAddress((void**)&wq_hi, g_wq_hi);
    cudaGetSymbolAddress((void**)&wq_lo, g_wq_lo);
    cudaGetSymbolAddress((void**)&wk_hi, g_wk_hi);
    cudaGetSymbolAddress((void**)&wk_lo, g_wk_lo);
    cudaGetSymbolAddress((void**)&wv_hi, g_wv_hi);
    cudaGetSymbolAddress((void**)&wv_lo, g_wv_lo);
    cudaGetSymbolAddress((void**)&wo_hi, g_wo_hi);
    cudaGetSymbolAddress((void**)&wo_lo, g_wo_lo);
    cudaGetSymbolAddress((void**)&w1_hi, g_w1_hi);
    cudaGetSymbolAddress((void**)&w1_lo, g_w1_lo);
    cudaGetSymbolAddress((void**)&w2_hi, g_w2_hi);
    cudaGetSymbolAddress((void**)&w2_lo, g_w2_lo);
    cudaGetSymbolAddress((void**)&wout_hi, g_wout_hi);
    cudaGetSymbolAddress((void**)&wout_lo, g_wout_lo);

    cudaFuncSetAttribute(hgemm_kernel<0>, cudaFuncAttributeMaxDynamicSharedMemorySize, GEMM_SMEM_BYTES);
    cudaFuncSetAttribute(hgemm_kernel<1>, cudaFuncAttributeMaxDynamicSharedMemorySize, GEMM_SMEM_BYTES);
    cudaFuncSetAttribute(hgemm_kernel<2>, cudaFuncAttributeMaxDynamicSharedMemorySize, GEMM_SMEM_BYTES);
    cudaFuncSetAttribute(hgemm_kernel<3>, cudaFuncAttributeMaxDynamicSharedMemorySize, GEMM_SMEM_BYTES);

    // split all weights (deterministic, every launch)
    split_launch(Wq, wq_hi, wq_lo, L_LAYERS * D_MODEL * P_PROJ);
    split_launch(Wk, wk_hi, wk_lo, L_LAYERS * D_MODEL * P_PROJ);
    split_launch(Wv, wv_hi, wv_lo, L_LAYERS * D_MODEL * P_PROJ);
    split_launch(Wo, wo_hi, wo_lo, L_LAYERS * P_PROJ * D_MODEL);
    split_launch(W1, w1_hi, w1_lo, L_LAYERS * D_MODEL * FF_DIM);
    split_launch(W2, w2_hi, w2_lo, L_LAYERS * FF_DIM * D_MODEL);
    split_launch(W_out, wout_hi, wout_lo, D_MODEL * V_VOCAB);

    const dim3 g768 (P_PROJ / BN, ROWS / BM);     // (6, 64)
    const dim3 gff  (FF_DIM / BN, ROWS / BM);     // (24, 64)
    const dim3 ghead(V_VOCAB / BN, ROWS / BM);    // (4, 64)
    const dim3 gattn(T_SEQ / 32, B_BATCH * N_HEADS);

    embed_kernel<<<ROWS, 256>>>(idx, tok_emb, pos_emb, x);

    for (int l = 0; l < L_LAYERS; l++) {
        const size_t wdp = (size_t)l * D_MODEL * P_PROJ;
        const size_t wdf = (size_t)l * D_MODEL * FF_DIM;

        layernorm_split_kernel<<<ROWS, 256>>>(x, ln1_g + l * D_MODEL, ln1_b + l * D_MODEL, h_hi, h_lo);

        hgemm_kernel<0><<<g768, 256, GEMM_SMEM_BYTES>>>(
            h_hi, h_lo, wq_hi + wdp, wq_lo + wdp, bq + l * P_PROJ, nullptr,
            q, nullptr, nullptr, ROWS, P_PROJ, D_MODEL);
        hgemm_kernel<0><<<g768, 256, GEMM_SMEM_BYTES>>>(
            h_hi, h_lo, wk_hi + wdp, wk_lo + wdp, bk + l * P_PROJ, nullptr,
            k, nullptr, nullptr, ROWS, P_PROJ, D_MODEL);
        hgemm_kernel<0><<<g768, 256, GEMM_SMEM_BYTES>>>(
            h_hi, h_lo, wv_hi + wdp, wv_lo + wdp, bv + l * P_PROJ, nullptr,
            v, nullptr, nullptr, ROWS, P_PROJ, D_MODEL);

        attn_kernel<<<gattn, 128>>>(q, k, v, attn_mask, y_hi, y_lo);

        // x = x + y @ Wo + bo
        hgemm_kernel<2><<<g768, 256, GEMM_SMEM_BYTES>>>(
            y_hi, y_lo, wo_hi + wdp, wo_lo + wdp, bo + l * D_MODEL, x,
            x, nullptr, nullptr, ROWS, D_MODEL, P_PROJ);

        layernorm_split_kernel<<<ROWS, 256>>>(x, ln2_g + l * D_MODEL, ln2_b + l * D_MODEL, h_hi, h_lo);

        // m1 = gelu(h @ W1 + b1) -> split bf16
        hgemm_kernel<1><<<gff, 256, GEMM_SMEM_BYTES>>>(
            h_hi, h_lo, w1_hi + wdf, w1_lo + wdf, b1 + l * FF_DIM, nullptr,
            nullptr, m1_hi, m1_lo, ROWS, FF_DIM, D_MODEL);
        // x = x + m1 @ W2 + b2
        hgemm_kernel<2><<<g768, 256, GEMM_SMEM_BYTES>>>(
            m1_hi, m1_lo, w2_hi + wdf, w2_lo + wdf, b2 + l * D_MODEL, x,
            x, nullptr, nullptr, ROWS, D_MODEL, FF_DIM);
    }

    layernorm_split_kernel<<<ROWS, 256>>>(x, lnf_g, lnf_b, h_hi, h_lo);
    hgemm_kernel<3><<<ghead, 256, GEMM_SMEM_BYTES>>>(
        h_hi, h_lo, wout_hi, wout_lo, nullptr, nullptr,
        out, nullptr, nullptr, ROWS, V_VOCAB, D_MODEL);
}

// round 4
// speedup vs baseline: 2.2156x; 1.0269x over previous
#include <cuda_runtime.h>
#include <cuda_bf16.h>
#include <math.h>
#include <stdint.h>

// ---------------------------------------------------------------------------
// Problem constants
// ---------------------------------------------------------------------------
#define L_LAYERS 6
#define V_VOCAB  512
#define D_MODEL  768
#define P_PROJ   768
#define N_HEADS  12
#define HD       64
#define FF_DIM   3072
#define B_BATCH  8
#define T_SEQ    1024
#define ROWS     (B_BATCH * T_SEQ)   // 8192
#define LN_EPS   1e-5f

// ---------------------------------------------------------------------------
// Scratch (device globals: allocation-free rule)
// ---------------------------------------------------------------------------
__device__ float g_x [ROWS * D_MODEL];           // residual stream (fp32)
__device__ float g_q [ROWS * P_PROJ];
__device__ float g_k [ROWS * P_PROJ];
__device__ float g_v [ROWS * P_PROJ];

__device__ __nv_bfloat16 g_h_hi [ROWS * D_MODEL];
__device__ __nv_bfloat16 g_h_lo [ROWS * D_MODEL];
__device__ __nv_bfloat16 g_y_hi [ROWS * P_PROJ];
__device__ __nv_bfloat16 g_y_lo [ROWS * P_PROJ];
__device__ __nv_bfloat16 g_m1_hi[ROWS * FF_DIM];
__device__ __nv_bfloat16 g_m1_lo[ROWS * FF_DIM];

// split weights
__device__ __nv_bfloat16 g_wq_hi[L_LAYERS * D_MODEL * P_PROJ];
__device__ __nv_bfloat16 g_wq_lo[L_LAYERS * D_MODEL * P_PROJ];
__device__ __nv_bfloat16 g_wk_hi[L_LAYERS * D_MODEL * P_PROJ];
__device__ __nv_bfloat16 g_wk_lo[L_LAYERS * D_MODEL * P_PROJ];
__device__ __nv_bfloat16 g_wv_hi[L_LAYERS * D_MODEL * P_PROJ];
__device__ __nv_bfloat16 g_wv_lo[L_LAYERS * D_MODEL * P_PROJ];
__device__ __nv_bfloat16 g_wo_hi[L_LAYERS * P_PROJ * D_MODEL];
__device__ __nv_bfloat16 g_wo_lo[L_LAYERS * P_PROJ * D_MODEL];
__device__ __nv_bfloat16 g_w1_hi[L_LAYERS * D_MODEL * FF_DIM];
__device__ __nv_bfloat16 g_w1_lo[L_LAYERS * D_MODEL * FF_DIM];
__device__ __nv_bfloat16 g_w2_hi[L_LAYERS * FF_DIM * D_MODEL];
__device__ __nv_bfloat16 g_w2_lo[L_LAYERS * FF_DIM * D_MODEL];
__device__ __nv_bfloat16 g_wout_hi[D_MODEL * V_VOCAB];
__device__ __nv_bfloat16 g_wout_lo[D_MODEL * V_VOCAB];

// ---------------------------------------------------------------------------
// Small helpers
// ---------------------------------------------------------------------------
__device__ __forceinline__ uint32_t smem_u32(const void* p) {
    return (uint32_t)__cvta_generic_to_shared(p);
}
__device__ __forceinline__ void cp_async16(uint32_t dst, const void* src) {
    asm volatile("cp.async.cg.shared.global [%0], [%1], 16;" :: "r"(dst), "l"(src));
}
__device__ __forceinline__ void cp_commit() {
    asm volatile("cp.async.commit_group;");
}
__device__ __forceinline__ void cp_wait1() {
    asm volatile("cp.async.wait_group 1;" ::: "memory");
}
__device__ __forceinline__ void cp_wait0() {
    asm volatile("cp.async.wait_group 0;" ::: "memory");
}
__device__ __forceinline__ void ldsm_x4(uint32_t* r, uint32_t addr) {
    asm volatile("ldmatrix.sync.aligned.m8n8.x4.shared.b16 {%0,%1,%2,%3}, [%4];"
                 : "=r"(r[0]), "=r"(r[1]), "=r"(r[2]), "=r"(r[3]) : "r"(addr));
}
__device__ __forceinline__ void ldsm_x4_t(uint32_t* r, uint32_t addr) {
    asm volatile("ldmatrix.sync.aligned.m8n8.x4.trans.shared.b16 {%0,%1,%2,%3}, [%4];"
                 : "=r"(r[0]), "=r"(r[1]), "=r"(r[2]), "=r"(r[3]) : "r"(addr));
}
__device__ __forceinline__ void mma_bf16(float* d, const uint32_t* a, uint32_t b0, uint32_t b1) {
    asm volatile("mma.sync.aligned.m16n8k16.row.col.f32.bf16.bf16.f32 "
                 "{%0,%1,%2,%3}, {%4,%5,%6,%7}, {%8,%9}, {%0,%1,%2,%3};"
                 : "+f"(d[0]), "+f"(d[1]), "+f"(d[2]), "+f"(d[3])
                 : "r"(a[0]), "r"(a[1]), "r"(a[2]), "r"(a[3]), "r"(b0), "r"(b1));
}
__device__ __forceinline__ float gelu_exact(float v) {
    return 0.5f * v * (1.0f + erff(v * 0.70710678118654752f));
}
__device__ __forceinline__ void split_store2(__nv_bfloat16* Hi, __nv_bfloat16* Lo,
                                             size_t off, float a, float b) {
    __nv_bfloat16 ha = __float2bfloat16(a), hb = __float2bfloat16(b);
    __nv_bfloat162 hv; hv.x = ha; hv.y = hb;
    *(__nv_bfloat162*)(Hi + off) = hv;
    __nv_bfloat162 lv;
    lv.x = __float2bfloat16(a - __bfloat162float(ha));
    lv.y = __float2bfloat16(b - __bfloat162float(hb));
    *(__nv_bfloat162*)(Lo + off) = lv;
}

// ---------------------------------------------------------------------------
// Weight split: fp32 -> (hi, lo) bf16, vectorized x4
// ---------------------------------------------------------------------------
__global__ void split_kernel(const float4* __restrict__ src,
                             __nv_bfloat16* __restrict__ hi,
                             __nv_bfloat16* __restrict__ lo, int n4)
{
    int i = blockIdx.x * 256 + threadIdx.x;
    if (i >= n4) return;
    float4 v = src[i];
    size_t off = (size_t)i * 4;
    split_store2(hi, lo, off,     v.x, v.y);
    split_store2(hi, lo, off + 2, v.z, v.w);
}

// ---------------------------------------------------------------------------
// Embedding
// ---------------------------------------------------------------------------
__global__ void embed_kernel(const int* __restrict__ idx,
                             const float* __restrict__ tok,
                             const float* __restrict__ pos,
                             float* __restrict__ x)
{
    int r = blockIdx.x;
    int t = r & (T_SEQ - 1);
    int token = idx[r];
    const float* te = tok + (size_t)token * D_MODEL;
    const float* pe = pos + (size_t)t * D_MODEL;
    float* xr = x + (size_t)r * D_MODEL;
    for (int c = threadIdx.x; c < D_MODEL; c += 256)
        xr[c] = te[c] + pe[c];
}

// ---------------------------------------------------------------------------
// LayerNorm -> split bf16 (hi, lo) output
// ---------------------------------------------------------------------------
__global__ __launch_bounds__(256) void layernorm_split_kernel(
    const float* __restrict__ x, const float* __restrict__ g,
    const float* __restrict__ b,
    __nv_bfloat16* __restrict__ ohi, __nv_bfloat16* __restrict__ olo)
{
    int row = blockIdx.x;
    const float* xr = x + (size_t)row * D_MODEL;
    int t = threadIdx.x;
    float v0 = xr[t], v1 = xr[t + 256], v2 = xr[t + 512];
    float s  = v0 + v1 + v2;
    float sq = v0 * v0 + v1 * v1 + v2 * v2;
    #pragma unroll
    for (int off = 16; off > 0; off >>= 1) {
        s  += __shfl_xor_sync(0xffffffffu, s,  off);
        sq += __shfl_xor_sync(0xffffffffu, sq, off);
    }
    __shared__ float ss[8], sqq[8];
    if ((t & 31) == 0) { ss[t >> 5] = s; sqq[t >> 5] = sq; }
    __syncthreads();
    float ts = 0.f, tsq = 0.f;
    #pragma unroll
    for (int i = 0; i < 8; i++) { ts += ss[i]; tsq += sqq[i]; }
    const float inv = 1.0f / (float)D_MODEL;
    float mu  = ts * inv;
    float var = tsq * inv - mu * mu;
    float r   = rsqrtf(var + LN_EPS);

    size_t base = (size_t)row * D_MODEL;
    #pragma unroll
    for (int i = 0; i < 3; i++) {
        int c = t + i * 256;
        float v = (i == 0 ? v0 : (i == 1 ? v1 : v2));
        float o = (v - mu) * r * g[c] + b[c];
        __nv_bfloat16 h = __float2bfloat16(o);
        ohi[base + c] = h;
        olo[base + c] = __float2bfloat16(o - __bfloat162float(h));
    }
}

// ---------------------------------------------------------------------------
// Split-bf16 tensor-core GEMM: C[M,N] = (Ahi+Alo) @ (Bhi+Blo)  (fp32 accum)
// 128x128x32 CTA tile, 8 warps (4x2), warp tile 32x64, m16n8k16 bf16 mma,
// cp.async double buffering, padded smem pitches for conflict-free ldmatrix.
// EPI: 0 = +bias -> f32 C
//      1 = +bias, exact GELU -> split bf16 (Chi, Clo)
//      2 = +bias +Res -> f32 C
//      3 = plain -> f32 C
// ---------------------------------------------------------------------------
#define BM 128
#define BN 128
#define BK 32
#define PA 40    // A smem pitch in bf16 (80 bytes)
#define PB 136   // B smem pitch in bf16 (272 bytes)
#define AS_ELEMS (BM * PA)                         // 5120
#define BS_ELEMS (BK * PB)                         // 4352
#define STAGE_ELEMS (2 * AS_ELEMS + 2 * BS_ELEMS)  // 18944
#define GEMM_SMEM_BYTES (2 * STAGE_ELEMS * 2)      // 75776

template <int EPI>
__global__ __launch_bounds__(256) void hgemm_kernel(
    const __nv_bfloat16* __restrict__ Ahi, const __nv_bfloat16* __restrict__ Alo,
    const __nv_bfloat16* __restrict__ Bhi, const __nv_bfloat16* __restrict__ Blo,
    const float* __restrict__ bias, const float* __restrict__ Res,
    float* __restrict__ C,
    __nv_bfloat16* __restrict__ Chi, __nv_bfloat16* __restrict__ Clo,
    int M, int N, int K)
{
    extern __shared__ __nv_bfloat16 sm[];
    const uint32_t smem_base = smem_u32(sm);
    const uint32_t stage_bytes = STAGE_ELEMS * 2;
    const uint32_t offAhi = 0;
    const uint32_t offAlo = AS_ELEMS * 2;
    const uint32_t offBhi = 2 * AS_ELEMS * 2;
    const uint32_t offBlo = (2 * AS_ELEMS + BS_ELEMS) * 2;

    const int tid  = threadIdx.x;
    const int lane = tid & 31;
    const int wid  = tid >> 5;
    const int warp_m = wid >> 1;        // 0..3
    const int warp_n = wid & 1;         // 0..1
    const int bm = blockIdx.y * BM;
    const int bn = blockIdx.x * BN;

    // global->smem load mapping
    const int a_row = tid >> 2;         // 0..63 (+64 on second pass)
    const int a_q   = tid & 3;
    const int b_row = tid >> 4;         // 0..15 (+16 on second pass)
    const int b_q   = tid & 15;

    float acc[2][8][4];
    #pragma unroll
    for (int i = 0; i < 2; i++)
        #pragma unroll
        for (int j = 0; j < 8; j++)
            #pragma unroll
            for (int t = 0; t < 4; t++) acc[i][j][t] = 0.f;

    const int n_tiles = K / BK;

    // stage loader
    auto load_stage = [&](int s, int k0) {
        uint32_t base = smem_base + s * stage_bytes;
        #pragma unroll
        for (int j = 0; j < 2; j++) {
            int ar = a_row + j * 64;
            const __nv_bfloat16* srcA = Ahi + (size_t)(bm + ar) * K + k0 + a_q * 8;
            uint32_t dstA = base + offAhi + (ar * PA + a_q * 8) * 2;
            cp_async16(dstA, srcA);
            const __nv_bfloat16* srcAl = Alo + (size_t)(bm + ar) * K + k0 + a_q * 8;
            cp_async16(dstA + (offAlo - offAhi), srcAl);

            int br = b_row + j * 16;
            const __nv_bfloat16* srcB = Bhi + (size_t)(k0 + br) * N + bn + b_q * 8;
            uint32_t dstB = base + offBhi + (br * PB + b_q * 8) * 2;
            cp_async16(dstB, srcB);
            const __nv_bfloat16* srcBl = Blo + (size_t)(k0 + br) * N + bn + b_q * 8;
            cp_async16(dstB + (offBlo - offBhi), srcBl);
        }
    };

    load_stage(0, 0);
    cp_commit();

    const int lr = lane & 15;
    const int lc = (lane >> 4) * 8;

    for (int t = 0; t < n_tiles; t++) {
        int cur = t & 1;
        if (t + 1 < n_tiles) {
            load_stage((t + 1) & 1, (t + 1) * BK);
            cp_commit();
            cp_wait1();
        } else {
            cp_wait0();
        }
        __syncthreads();

        uint32_t base = smem_base + cur * stage_bytes;
        #pragma unroll
        for (int ks = 0; ks < BK; ks += 16) {
            uint32_t a_hi[2][4], a_lo[2][4];
            #pragma unroll
            for (int mi = 0; mi < 2; mi++) {
                uint32_t addr = base + offAhi +
                    ((warp_m * 32 + mi * 16 + lr) * PA + ks + lc) * 2;
                ldsm_x4(a_hi[mi], addr);
                ldsm_x4(a_lo[mi], addr + (offAlo - offAhi));
            }
            uint32_t b_hi[4][4], b_lo[4][4];
            #pragma unroll
            for (int bi = 0; bi < 4; bi++) {
                uint32_t addr = base + offBhi +
                    ((ks + lr) * PB + warp_n * 64 + bi * 16 + lc) * 2;
                ldsm_x4_t(b_hi[bi], addr);
                ldsm_x4_t(b_lo[bi], addr + (offBlo - offBhi));
            }
            #pragma unroll
            for (int mi = 0; mi < 2; mi++) {
                #pragma unroll
                for (int ni = 0; ni < 8; ni++) {
                    int bi = ni >> 1;
                    int hh = (ni & 1) * 2;
                    mma_bf16(acc[mi][ni], a_hi[mi], b_hi[bi][hh], b_hi[bi][hh + 1]);
                    mma_bf16(acc[mi][ni], a_hi[mi], b_lo[bi][hh], b_lo[bi][hh + 1]);
                    mma_bf16(acc[mi][ni], a_lo[mi], b_hi[bi][hh], b_hi[bi][hh + 1]);
                }
            }
        }
        __syncthreads();
    }

    // epilogue
    const int g = lane >> 2, tig = lane & 3;
    #pragma unroll
    for (int mi = 0; mi < 2; mi++) {
        #pragma unroll
        for (int ni = 0; ni < 8; ni++) {
            int r0 = bm + warp_m * 32 + mi * 16 + g;
            int r1 = r0 + 8;
            int c  = bn + warp_n * 64 + ni * 8 + tig * 2;
            float v00 = acc[mi][ni][0], v01 = acc[mi][ni][1];
            float v10 = acc[mi][ni][2], v11 = acc[mi][ni][3];
            if (EPI != 3) {
                float b0 = bias[c], b1 = bias[c + 1];
                v00 += b0; v01 += b1; v10 += b0; v11 += b1;
            }
            if (EPI == 1) {
                v00 = gelu_exact(v00); v01 = gelu_exact(v01);
                v10 = gelu_exact(v10); v11 = gelu_exact(v11);
                split_store2(Chi, Clo, (size_t)r0 * N + c, v00, v01);
                split_store2(Chi, Clo, (size_t)r1 * N + c, v10, v11);
            } else {
                if (EPI == 2) {
                    float2 z0 = *(const float2*)&Res[(size_t)r0 * N + c];
                    float2 z1 = *(const float2*)&Res[(size_t)r1 * N + c];
                    v00 += z0.x; v01 += z0.y; v10 += z1.x; v11 += z1.y;
                }
                float2 o0 = make_float2(v00, v01);
                float2 o1 = make_float2(v10, v11);
                *(float2*)&C[(size_t)r0 * N + c] = o0;
                *(float2*)&C[(size_t)r1 * N + c] = o1;
            }
        }
    }
}

// ---------------------------------------------------------------------------
// Attention (fp32 math, split bf16 output)
// ---------------------------------------------------------------------------
__global__ __launch_bounds__(128) void attn_kernel(
    const float* __restrict__ Q, const float* __restrict__ K,
    const float* __restrict__ V, const float* __restrict__ mask,
    __nv_bfloat16* __restrict__ Yhi, __nv_bfloat16* __restrict__ Ylo)
{
    const int b  = blockIdx.y / N_HEADS;
    const int h  = blockIdx.y % N_HEADS;
    const int qb = blockIdx.x * 32;

    __shared__ float Qs[32][68];
    __shared__ float Ks[32][68];
    __shared__ float Vs[32][68];
    __shared__ float Ms[32];

    const int tid = threadIdx.x;
    const int ql  = tid >> 2;
    const int seg = tid & 3;

    #pragma unroll
    for (int i = 0; i < 4; i++) {
        int f = tid + i * 128;
        int r = f >> 4, c4 = (f & 15) << 2;
        size_t gi = (((size_t)b * T_SEQ + qb + r) * N_HEADS + h) * HD + c4;
        float4 qv = *(const float4*)&Q[gi];
        qv.x *= 0.125f; qv.y *= 0.125f; qv.z *= 0.125f; qv.w *= 0.125f;
        *(float4*)&Qs[r][c4] = qv;
    }

    float m = -1e30f, l = 0.f;
    float acc[64];
    #pragma unroll
    for (int d = 0; d < 64; d++) acc[d] = 0.f;

    for (int kb = 0; kb <= qb + 31; kb += 32) {
        __syncthreads();
        #pragma unroll
        for (int i = 0; i < 4; i++) {
            int f = tid + i * 128;
            int r = f >> 4, c4 = (f & 15) << 2;
            size_t gi = (((size_t)b * T_SEQ + kb + r) * N_HEADS + h) * HD + c4;
            *(float4*)&Ks[r][c4] = *(const float4*)&K[gi];
            *(float4*)&Vs[r][c4] = *(const float4*)&V[gi];
        }
        if (tid < 32) Ms[tid] = mask[b * T_SEQ + kb + tid];
        __syncthreads();

        float s[8];
        #pragma unroll
        for (int j = 0; j < 8; j++) s[j] = 0.f;
        #pragma unroll
        for (int d4 = 0; d4 < 16; d4++) {
            float4 qv = *(const float4*)&Qs[ql][d4 * 4];
            #pragma unroll
            for (int j = 0; j < 8; j++) {
                float4 kv = *(const float4*)&Ks[j * 4 + seg][d4 * 4];
                s[j] = fmaf(qv.x, kv.x, fmaf(qv.y, kv.y,
                       fmaf(qv.z, kv.z, fmaf(qv.w, kv.w, s[j]))));
            }
        }
        #pragma unroll
        for (int j = 0; j < 8; j++) {
            int kl = j * 4 + seg;
            int kg = kb + kl;
            if (kg > qb + ql || Ms[kl] == 0.f) s[j] = -1e30f;
        }

        float tm = s[0];
        #pragma unroll
        for (int j = 1; j < 8; j++) tm = fmaxf(tm, s[j]);
        tm = fmaxf(tm, __shfl_xor_sync(0xffffffffu, tm, 1));
        tm = fmaxf(tm, __shfl_xor_sync(0xffffffffu, tm, 2));

        float nm   = fmaxf(m, tm);
        float corr = __expf(m - nm);
        float p[8], ps = 0.f;
        #pragma unroll
        for (int j = 0; j < 8; j++) { p[j] = __expf(s[j] - nm); ps += p[j]; }
        ps += __shfl_xor_sync(0xffffffffu, ps, 1);
        ps += __shfl_xor_sync(0xffffffffu, ps, 2);
        l = l * corr + ps;
        m = nm;

        #pragma unroll
        for (int d4 = 0; d4 < 16; d4++) {
            float ax = acc[d4 * 4 + 0] * corr;
            float ay = acc[d4 * 4 + 1] * corr;
            float az = acc[d4 * 4 + 2] * corr;
            float aw = acc[d4 * 4 + 3] * corr;
            #pragma unroll
            for (int j = 0; j < 8; j++) {
                float4 vv = *(const float4*)&Vs[j * 4 + seg][d4 * 4];
                ax = fmaf(p[j], vv.x, ax);
                ay = fmaf(p[j], vv.y, ay);
                az = fmaf(p[j], vv.z, az);
                aw = fmaf(p[j], vv.w, aw);
            }
            acc[d4 * 4 + 0] = ax; acc[d4 * 4 + 1] = ay;
            acc[d4 * 4 + 2] = az; acc[d4 * 4 + 3] = aw;
        }
    }

    float invl = 1.0f / l;
    size_t ybase = (((size_t)b * T_SEQ + qb + ql) * N_HEADS + h) * HD;
    #pragma unroll
    for (int d = 0; d < 64; d++) {
        float v = acc[d];
        v += __shfl_xor_sync(0xffffffffu, v, 1);
        v += __shfl_xor_sync(0xffffffffu, v, 2);
        if (seg == (d & 3)) {
            float o = v * invl;
            __nv_bfloat16 hh = __float2bfloat16(o);
            Yhi[ybase + d] = hh;
            Ylo[ybase + d] = __float2bfloat16(o - __bfloat162float(hh));
        }
    }
}

// ---------------------------------------------------------------------------
// Host orchestration
// ---------------------------------------------------------------------------
static void split_launch(const float* src, __nv_bfloat16* hi, __nv_bfloat16* lo, int n) {
    int n4 = n / 4;
    split_kernel<<<(n4 + 255) / 256, 256>>>((const float4*)src, hi, lo, n4);
}

extern "C" void kernel_launch(void* const* d_in, const int* in_sizes, int n_in,
                              void* d_out, int out_size)
{
    const int*   idx       = (const int*)  d_in[0];
    const float* attn_mask = (const float*)d_in[1];
    const float* tok_emb   = (const float*)d_in[2];
    const float* pos_emb   = (const float*)d_in[3];
    const float* ln1_g     = (const float*)d_in[4];
    const float* ln1_b     = (const float*)d_in[5];
    const float* Wq        = (const float*)d_in[6];
    const float* bq        = (const float*)d_in[7];
    const float* Wk        = (const float*)d_in[8];
    const float* bk        = (const float*)d_in[9];
    const float* Wv        = (const float*)d_in[10];
    const float* bv        = (const float*)d_in[11];
    const float* Wo        = (const float*)d_in[12];
    const float* bo        = (const float*)d_in[13];
    const float* ln2_g     = (const float*)d_in[14];
    const float* ln2_b     = (const float*)d_in[15];
    const float* W1        = (const float*)d_in[16];
    const float* b1        = (const float*)d_in[17];
    const float* W2        = (const float*)d_in[18];
    const float* b2        = (const float*)d_in[19];
    const float* lnf_g     = (const float*)d_in[20];
    const float* lnf_b     = (const float*)d_in[21];
    const float* W_out     = (const float*)d_in[22];
    float* out = (float*)d_out;

    float *x, *q, *k, *v;
    __nv_bfloat16 *h_hi, *h_lo, *y_hi, *y_lo, *m1_hi, *m1_lo;
    __nv_bfloat16 *wq_hi, *wq_lo, *wk_hi, *wk_lo, *wv_hi, *wv_lo;
    __nv_bfloat16 *wo_hi, *wo_lo, *w1_hi, *w1_lo, *w2_hi, *w2_lo, *wout_hi, *wout_lo;

    cudaGetSymbolAddress((void**)&x,  g_x);
    cudaGetSymbolAddress((void**)&q,  g_q);
    cudaGetSymbolAddress((void**)&k,  g_k);
    cudaGetSymbolAddress((void**)&v,  g_v);
    cudaGetSymbolAddress((void**)&h_hi,  g_h_hi);
    cudaGetSymbolAddress((void**)&h_lo,  g_h_lo);
    cudaGetSymbolAddress((void**)&y_hi,  g_y_hi);
    cudaGetSymbolAddress((void**)&y_lo,  g_y_lo);
    cudaGetSymbolAddress((void**)&m1_hi, g_m1_hi);
    cudaGetSymbolAddress((void**)&m1_lo, g_m1_lo);
    cudaGetSymbolAddress((void**)&wq_hi, g_wq_hi);
    cudaGetSymbolAddress((void**)&wq_lo, g_wq_lo);
    cudaGetSymbolAddress((void**)&wk_hi, g_wk_hi);
    cudaGetSymbolAddress((void**)&wk_lo, g_wk_lo);
    cudaGetSymbolAddress((void**)&wv_hi, g_wv_hi);
    cudaGetSymbolAddress((void**)&wv_lo, g_wv_lo);
    cudaGetSymbolAddress((void**)&wo_hi, g_wo_hi);
    cudaGetSymbolAddress((void**)&wo_lo, g_wo_lo);
    cudaGetSymbolAddress((void**)&w1_hi, g_w1_hi);
    cudaGetSymbolAddress((void**)&w1_lo, g_w1_lo);
    cudaGetSymbolAddress((void**)&w2_hi, g_w2_hi);
    cudaGetSymbolAddress((void**)&w2_lo, g_w2_lo);
    cudaGetSymbolAddress((void**)&wout_hi, g_wout_hi);
    cudaGetSymbolAddress((void**)&wout_lo, g_wout_lo);

    cudaFuncSetAttribute(hgemm_kernel<0>, cudaFuncAttributeMaxDynamicSharedMemorySize, GEMM_SMEM_BYTES);
    cudaFuncSetAttribute(hgemm_kernel<1>, cudaFuncAttributeMaxDynamicSharedMemorySize, GEMM_SMEM_BYTES);
    cudaFuncSetAttribute(hgemm_kernel<2>, cudaFuncAttributeMaxDynamicSharedMemorySize, GEMM_SMEM_BYTES);
    cudaFuncSetAttribute(hgemm_kernel<3>, cudaFuncAttributeMaxDynamicSharedMemorySize, GEMM_SMEM_BYTES);

    // split all weights (deterministic, every launch)
    split_launch(Wq, wq_hi, wq_lo, L_LAYERS * D_MODEL * P_PROJ);
    split_launch(Wk, wk_hi, wk_lo, L_LAYERS * D_MODEL * P_PROJ);
    split_launch(Wv, wv_hi, wv_lo, L_LAYERS * D_MODEL * P_PROJ);
    split_launch(Wo, wo_hi, wo_lo, L_LAYERS * P_PROJ * D_MODEL);
    split_launch(W1, w1_hi, w1_lo, L_LAYERS * D_MODEL * FF_DIM);
    split_launch(W2, w2_hi, w2_lo, L_LAYERS * FF_DIM * D_MODEL);
    split_launch(W_out, wout_hi, wout_lo, D_MODEL * V_VOCAB);

    const dim3 g768 (P_PROJ / BN, ROWS / BM);     // (6, 64)
    const dim3 gff  (FF_DIM / BN, ROWS / BM);     // (24, 64)
    const dim3 ghead(V_VOCAB / BN, ROWS / BM);    // (4, 64)
    const dim3 gattn(T_SEQ / 32, B_BATCH * N_HEADS);

    embed_kernel<<<ROWS, 256>>>(idx, tok_emb, pos_emb, x);

    for (int l = 0; l < L_LAYERS; l++) {
        const size_t wdp = (size_t)l * D_MODEL * P_PROJ;
        const size_t wdf = (size_t)l * D_MODEL * FF_DIM;

        layernorm_split_kernel<<<ROWS, 256>>>(x, ln1_g + l * D_MODEL, ln1_b + l * D_MODEL, h_hi, h_lo);

        hgemm_kernel<0><<<g768, 256, GEMM_SMEM_BYTES>>>(
            h_hi, h_lo, wq_hi + wdp, wq_lo + wdp, bq + l * P_PROJ, nullptr,
            q, nullptr, nullptr, ROWS, P_PROJ, D_MODEL);
        hgemm_kernel<0><<<g768, 256, GEMM_SMEM_BYTES>>>(
            h_hi, h_lo, wk_hi + wdp, wk_lo + wdp, bk + l * P_PROJ, nullptr,
            k, nullptr, nullptr, ROWS, P_PROJ, D_MODEL);
        hgemm_kernel<0><<<g768, 256, GEMM_SMEM_BYTES>>>(
            h_hi, h_lo, wv_hi + wdp, wv_lo + wdp, bv + l * P_PROJ, nullptr,
            v, nullptr, nullptr, ROWS, P_PROJ, D_MODEL);

        attn_kernel<<<gattn, 128>>>(q, k, v, attn_mask, y_hi, y_lo);

        // x = x + y @ Wo + bo
        hgemm_kernel<2><<<g768, 256, GEMM_SMEM_BYTES>>>(
            y_hi, y_lo, wo_hi + wdp, wo_lo + wdp, bo + l * D_MODEL, x,
            x, nullptr, nullptr, ROWS, D_MODEL, P_PROJ);

        layernorm_split_kernel<<<ROWS, 256>>>(x, ln2_g + l * D_MODEL, ln2_b + l * D_MODEL, h_hi, h_lo);

        // m1 = gelu(h @ W1 + b1) -> split bf16
        hgemm_kernel<1><<<gff, 256, GEMM_SMEM_BYTES>>>(
            h_hi, h_lo, w1_hi + wdf, w1_lo + wdf, b1 + l * FF_DIM, nullptr,
            nullptr, m1_hi, m1_lo, ROWS, FF_DIM, D_MODEL);
        // x = x + m1 @ W2 + b2
        hgemm_kernel<2><<<g768, 256, GEMM_SMEM_BYTES>>>(
            m1_hi, m1_lo, w2_hi + wdf, w2_lo + wdf, b2 + l * D_MODEL, x,
            x, nullptr, nullptr, ROWS, D_MODEL, FF_DIM);
    }

    layernorm_split_kernel<<<ROWS, 256>>>(x, lnf_g, lnf_b, h_hi, h_lo);
    hgemm_kernel<3><<<ghead, 256, GEMM_SMEM_BYTES>>>(
        h_hi, h_lo, wout_hi, wout_lo, nullptr, nullptr,
        out, nullptr, nullptr, ROWS, V_VOCAB, D_MODEL);
}